// round 2
// baseline (speedup 1.0000x reference)
#include <cuda_runtime.h>
#include <math.h>

#define WAYS 5
#define NQ 75
#define CIN 640
#define NT 512
#define CP 64
#define NP (NQ*WAYS)   // 375

// ---------------- scratch (__device__ globals; no runtime allocation) ----------------
__device__ float g_wt[CIN*CP];          // transposed conv weight [c][o]
__device__ float g_wsum[CP];
__device__ float g_bnscale[CP];
__device__ float g_bnshift[CP];
__device__ float g_feat_s[WAYS*CP*NT];  // [w][o][i]
__device__ float g_feat_q[NQ*CP*NT];    // [q][o][k]
__device__ float g_mu_s[WAYS*NT];
__device__ float g_mu_q[NQ*NT];
__device__ float g_corr[(size_t)NP*NT*NT];   // 393 MB
__device__ float g_cmax[NP*NT], g_cscale[NP*NT];
__device__ float g_rmax[NP*NT], g_rscale[NP*NT];
__device__ float g_zcol[NP*NT], g_zrow[NP*NT];
__device__ float g_as[NP*NT], g_aq[NP*NT];
__device__ float g_bs[NP], g_bq[NP];
__device__ float g_ps[NP*CIN], g_pq[NP*CIN];

// ---------------- k0: weight transpose + row sums + BN fold ----------------
__global__ void k0_prep(const float* __restrict__ w, const float* __restrict__ gamma,
                        const float* __restrict__ beta, const float* __restrict__ mean,
                        const float* __restrict__ var) {
    int t = threadIdx.x;
    for (int idx = t; idx < CIN*CP; idx += blockDim.x) {
        int c = idx / CP, o = idx % CP;
        g_wt[idx] = w[o*CIN + c];
    }
    if (t < CP) {
        float s = 0.f;
        const float* row = w + t*CIN;
        #pragma unroll 8
        for (int c = 0; c < CIN; c++) s += row[c];
        g_wsum[t] = s;
        float sc = gamma[t] * rsqrtf(var[t] + 1e-5f);
        g_bnscale[t] = sc;
        g_bnshift[t] = beta[t] - mean[t]*sc;
    }
}

// ---------------- k1: center+conv+BN+ReLU+L2norm features ----------------
// grid (4, 80): y = batch (0..4 support, 5..79 query), x = token block of 128
__global__ void k1_feat(const float* __restrict__ spt, const float* __restrict__ qry) {
    __shared__ float wb[16][CP];
    __shared__ float sc[CP], sh[CP], ws[CP];
    int t = threadIdx.x;               // 128
    int b = blockIdx.y;
    int i = blockIdx.x*128 + t;
    const float* X = (b < WAYS) ? (spt + (size_t)b*CIN*NT)
                                : (qry + (size_t)(b-WAYS)*CIN*NT);
    if (t < CP) { sc[t] = g_bnscale[t]; sh[t] = g_bnshift[t]; ws[t] = g_wsum[t]; }
    float acc[CP];
    #pragma unroll
    for (int o = 0; o < CP; o++) acc[o] = 0.f;
    float xsum = 0.f;
    for (int c0 = 0; c0 < CIN; c0 += 16) {
        __syncthreads();
        #pragma unroll
        for (int j = 0; j < 8; j++) {
            int idx = t + j*128;
            ((float*)wb)[idx] = g_wt[c0*CP + idx];
        }
        __syncthreads();
        #pragma unroll 4
        for (int cc = 0; cc < 16; cc++) {
            float x = X[(size_t)(c0+cc)*NT + i];
            xsum += x;
            #pragma unroll
            for (int o = 0; o < CP; o++) acc[o] = fmaf(x, wb[cc][o], acc[o]);
        }
    }
    float mu = xsum * (1.f/CIN);
    if (b < WAYS) g_mu_s[b*NT + i] = mu; else g_mu_q[(b-WAYS)*NT + i] = mu;
    float nrm = 0.f;
    #pragma unroll
    for (int o = 0; o < CP; o++) {
        float v = (acc[o] - mu*ws[o]) * sc[o] + sh[o];
        v = fmaxf(v, 0.f);
        acc[o] = v;
        nrm = fmaf(v, v, nrm);
    }
    float inv = 1.f / fmaxf(sqrtf(nrm), 1e-8f);
    float* F = (b < WAYS) ? (g_feat_s + (size_t)b*CP*NT)
                          : (g_feat_q + (size_t)(b-WAYS)*CP*NT);
    #pragma unroll
    for (int o = 0; o < CP; o++) F[o*NT + i] = acc[o]*inv;
}

// ---------------- k2: corr GEMM  corr[p][i][k] = sum_o spt[w][o][i]*qry[q][o][k] ----------------
// grid (4 kblk, 4 iblk, 375 p), 256 threads, 128x128 tile, K=64 full depth
__global__ void k2_corr() {
    extern __shared__ float smem[];
    float* As = smem;            // [64][128]
    float* Bs = smem + 64*128;   // [64][128]
    int t = threadIdx.x;
    int p = blockIdx.z;
    int q = p / WAYS, w = p % WAYS;
    int i0 = blockIdx.y * 128, k0 = blockIdx.x * 128;
    const float* A = g_feat_s + (size_t)w*CP*NT + i0;
    const float* B = g_feat_q + (size_t)q*CP*NT + k0;
    int c4 = t & 31, orow = t >> 5;
    #pragma unroll
    for (int r = 0; r < 8; r++) {
        int o = orow + r*8;
        float4 av = *(const float4*)(A + (size_t)o*NT + c4*4);
        float4 bv = *(const float4*)(B + (size_t)o*NT + c4*4);
        *(float4*)(As + o*128 + c4*4) = av;
        *(float4*)(Bs + o*128 + c4*4) = bv;
    }
    __syncthreads();
    int tx = t & 15, ty = t >> 4;
    float acc[8][8];
    #pragma unroll
    for (int m = 0; m < 8; m++)
        #pragma unroll
        for (int n = 0; n < 8; n++) acc[m][n] = 0.f;
    #pragma unroll 4
    for (int o = 0; o < 64; o++) {
        float a[8], b[8];
        #pragma unroll
        for (int m = 0; m < 8; m++) a[m] = As[o*128 + ty + 16*m];
        #pragma unroll
        for (int n = 0; n < 8; n++) b[n] = Bs[o*128 + tx + 16*n];
        #pragma unroll
        for (int m = 0; m < 8; m++)
            #pragma unroll
            for (int n = 0; n < 8; n++) acc[m][n] = fmaf(a[m], b[n], acc[m][n]);
    }
    float* out = g_corr + (size_t)p*NT*NT;
    #pragma unroll
    for (int m = 0; m < 8; m++) {
        int i = i0 + ty + 16*m;
        #pragma unroll
        for (int n = 0; n < 8; n++)
            out[(size_t)i*NT + (k0 + tx + 16*n)] = acc[m][n];
    }
}

// ---------------- k3: per-row / per-col max + softmax scale (gaussian-normalize folded) ------
// grid 375, 256 threads. thread t owns cols t, t+256. warp wp owns row blk*8+wp.
__global__ void k3_stats() {
    __shared__ float tile[8*NT];
    int t = threadIdx.x, lane = t & 31, wp = t >> 5;
    int p = blockIdx.x;
    const float* M = g_corr + (size_t)p*NT*NT;
    float cs[2] = {0,0}, cs2[2] = {0,0}, cm[2] = {-1e30f,-1e30f};
    for (int blk = 0; blk < 64; blk++) {
        const float4* src = (const float4*)(M + (size_t)blk*8*NT);
        #pragma unroll
        for (int j = 0; j < 4; j++) ((float4*)tile)[t + 256*j] = src[t + 256*j];
        __syncthreads();
        #pragma unroll
        for (int r = 0; r < 8; r++)
            #pragma unroll
            for (int u = 0; u < 2; u++) {
                float v = tile[r*NT + t + 256*u];
                cs[u] += v; cs2[u] = fmaf(v, v, cs2[u]); cm[u] = fmaxf(cm[u], v);
            }
        float rs = 0, rs2 = 0, rm = -1e30f;
        #pragma unroll
        for (int j = 0; j < 16; j++) {
            float v = tile[wp*NT + lane + 32*j];
            rs += v; rs2 = fmaf(v, v, rs2); rm = fmaxf(rm, v);
        }
        #pragma unroll
        for (int off = 16; off > 0; off >>= 1) {
            rs  += __shfl_xor_sync(0xffffffff, rs,  off);
            rs2 += __shfl_xor_sync(0xffffffff, rs2, off);
            rm   = fmaxf(rm, __shfl_xor_sync(0xffffffff, rm, off));
        }
        if (lane == 0) {
            int i = blk*8 + wp;
            float m = rs * (1.f/NT);
            float var = (rs2 - NT*m*m) * (1.f/(NT-1));
            g_rmax[p*NT + i] = rm;
            g_rscale[p*NT + i] = 1.f / (5.0f * sqrtf(var + 1e-5f));
        }
        __syncthreads();
    }
    #pragma unroll
    for (int u = 0; u < 2; u++) {
        int k = t + 256*u;
        float m = cs[u] * (1.f/NT);
        float var = (cs2[u] - NT*m*m) * (1.f/(NT-1));
        g_cmax[p*NT + k] = cm[u];
        g_cscale[p*NT + k] = 1.f / (5.0f * sqrtf(var + 1e-5f));
    }
}

// ---------------- k4: softmax partition sums Zcol (over i) and Zrow (over k) ----------------
__global__ void k4_z() {
    __shared__ float tile[8*NT];
    int t = threadIdx.x, lane = t & 31, wp = t >> 5;
    int p = blockIdx.x;
    const float* M = g_corr + (size_t)p*NT*NT;
    float cmx[2], csc[2], zc[2] = {0,0};
    #pragma unroll
    for (int u = 0; u < 2; u++) { cmx[u] = g_cmax[p*NT + t + 256*u]; csc[u] = g_cscale[p*NT + t + 256*u]; }
    for (int blk = 0; blk < 64; blk++) {
        const float4* src = (const float4*)(M + (size_t)blk*8*NT);
        #pragma unroll
        for (int j = 0; j < 4; j++) ((float4*)tile)[t + 256*j] = src[t + 256*j];
        __syncthreads();
        #pragma unroll
        for (int r = 0; r < 8; r++)
            #pragma unroll
            for (int u = 0; u < 2; u++) {
                float v = tile[r*NT + t + 256*u];
                zc[u] += __expf((v - cmx[u]) * csc[u]);
            }
        int i = blk*8 + wp;
        float rm = g_rmax[p*NT + i], rsc = g_rscale[p*NT + i];
        float zr = 0;
        #pragma unroll
        for (int j = 0; j < 16; j++) {
            float v = tile[wp*NT + lane + 32*j];
            zr += __expf((v - rm) * rsc);
        }
        #pragma unroll
        for (int off = 16; off > 0; off >>= 1) zr += __shfl_xor_sync(0xffffffff, zr, off);
        if (lane == 0) g_zrow[p*NT + i] = zr;
        __syncthreads();
    }
    g_zcol[p*NT + t] = zc[0];
    g_zcol[p*NT + t + 256] = zc[1];
}

// ---------------- k5: attn_s[i] = sum_k e_col/Zcol[k];  attn_q[k] = sum_i e_row/Zrow[i] -------
__global__ void k5_attn() {
    __shared__ float tile[8*NT];
    __shared__ float cmS[NT], cscS[NT], czS[NT];
    __shared__ float rmS[8], rscS[8], rzS[8];
    int t = threadIdx.x, lane = t & 31, wp = t >> 5;
    int p = blockIdx.x;
    const float* M = g_corr + (size_t)p*NT*NT;
    #pragma unroll
    for (int u = 0; u < 2; u++) {
        int k = t + 256*u;
        cmS[k] = g_cmax[p*NT + k];
        cscS[k] = g_cscale[p*NT + k];
        czS[k] = 1.f / g_zcol[p*NT + k];
    }
    float aq[2] = {0,0};
    for (int blk = 0; blk < 64; blk++) {
        const float4* src = (const float4*)(M + (size_t)blk*8*NT);
        #pragma unroll
        for (int j = 0; j < 4; j++) ((float4*)tile)[t + 256*j] = src[t + 256*j];
        if (t < 8) {
            int i = blk*8 + t;
            rmS[t] = g_rmax[p*NT + i];
            rscS[t] = g_rscale[p*NT + i];
            rzS[t] = 1.f / g_zrow[p*NT + i];
        }
        __syncthreads();
        #pragma unroll
        for (int r = 0; r < 8; r++) {
            float rm = rmS[r], rsc = rscS[r], rz = rzS[r];
            #pragma unroll
            for (int u = 0; u < 2; u++) {
                float v = tile[r*NT + t + 256*u];
                aq[u] += __expf((v - rm) * rsc) * rz;
            }
        }
        float as = 0;
        #pragma unroll
        for (int j = 0; j < 16; j++) {
            int k = lane + 32*j;
            float v = tile[wp*NT + k];
            as += __expf((v - cmS[k]) * cscS[k]) * czS[k];
        }
        #pragma unroll
        for (int off = 16; off > 0; off >>= 1) as += __shfl_xor_sync(0xffffffff, as, off);
        if (lane == 0) g_as[p*NT + blk*8 + wp] = as;
        __syncthreads();
    }
    g_aq[p*NT + t] = aq[0];
    g_aq[p*NT + t + 256] = aq[1];
}

// ---------------- k5b: mean-correction terms  bs = sum_i a_s*mu_s,  bq = sum_k a_q*mu_q -------
__global__ void k5b_bias() {
    int t = threadIdx.x, lane = t & 31, wp = t >> 5;
    int p = blockIdx.x*8 + wp;
    if (p >= NP) return;
    int q = p / WAYS, w = p % WAYS;
    float bs = 0, bq = 0;
    #pragma unroll
    for (int j = 0; j < 16; j++) {
        int k = lane + 32*j;
        bs = fmaf(g_as[p*NT + k], g_mu_s[w*NT + k], bs);
        bq = fmaf(g_aq[p*NT + k], g_mu_q[q*NT + k], bq);
    }
    #pragma unroll
    for (int off = 16; off > 0; off >>= 1) {
        bs += __shfl_xor_sync(0xffffffff, bs, off);
        bq += __shfl_xor_sync(0xffffffff, bq, off);
    }
    if (lane == 0) { g_bs[p] = bs; g_bq[p] = bq; }
}

// ---------------- k6a: support pooling  ps[p][c] = (sum_i a_s[p][i]*tok_s[w][c][i] - bs)/512 --
// grid (10 cblk, 5 w), 256 threads
__global__ void k6a_pool_s(const float* __restrict__ spt) {
    __shared__ float Tsm[64][65];
    __shared__ float Asm[75][64];
    int t = threadIdx.x;
    int w = blockIdx.y, c0 = blockIdx.x*64;
    int c = t & 63, qg = t >> 6;   // 0..3
    float acc[19];
    #pragma unroll
    for (int j = 0; j < 19; j++) acc[j] = 0.f;
    const float* T = spt + (size_t)w*CIN*NT;
    for (int ic = 0; ic < NT; ic += 64) {
        #pragma unroll
        for (int j = 0; j < 4; j++) {
            int f4 = t + 256*j;
            int row = f4 >> 4, col4 = f4 & 15;
            float4 v = *(const float4*)(T + (size_t)(c0+row)*NT + ic + col4*4);
            Tsm[row][col4*4+0] = v.x; Tsm[row][col4*4+1] = v.y;
            Tsm[row][col4*4+2] = v.z; Tsm[row][col4*4+3] = v.w;
        }
        for (int idx = t; idx < 75*64; idx += 256) {
            int qq = idx >> 6, ii = idx & 63;
            Asm[qq][ii] = g_as[(size_t)(qq*WAYS + w)*NT + ic + ii];
        }
        __syncthreads();
        #pragma unroll 8
        for (int i = 0; i < 64; i++) {
            float tv = Tsm[c][i];
            #pragma unroll
            for (int j = 0; j < 19; j++) {
                int qq = qg + 4*j;
                if (qq < 75) acc[j] = fmaf(Asm[qq][i], tv, acc[j]);
            }
        }
        __syncthreads();
    }
    #pragma unroll
    for (int j = 0; j < 19; j++) {
        int qq = qg + 4*j;
        if (qq < 75) {
            int p = qq*WAYS + w;
            g_ps[(size_t)p*CIN + c0 + c] = (acc[j] - g_bs[p]) * (1.f/NT);
        }
    }
}

// ---------------- k6b: query pooling  pq[p][c] = (sum_k a_q[p][k]*tok_q[q][c][k] - bq)/512 ----
// grid (10 cblk, 75 q), 320 threads (64 c x 5 w)
__global__ void k6b_pool_q(const float* __restrict__ qry) {
    __shared__ float Tsm[64][65];
    __shared__ float Aq[5*NT];
    int t = threadIdx.x;
    int q = blockIdx.y, c0 = blockIdx.x*64;
    int c = t & 63, w = t >> 6;
    for (int idx = t; idx < 5*NT; idx += 320) {
        int ww = idx >> 9, kk = idx & 511;
        Aq[idx] = g_aq[(size_t)(q*WAYS + ww)*NT + kk];
    }
    const float* T = qry + (size_t)q*CIN*NT;
    float acc = 0.f;
    for (int kc = 0; kc < NT; kc += 64) {
        for (int f4 = t; f4 < 1024; f4 += 320) {
            int row = f4 >> 4, col4 = f4 & 15;
            float4 v = *(const float4*)(T + (size_t)(c0+row)*NT + kc + col4*4);
            Tsm[row][col4*4+0] = v.x; Tsm[row][col4*4+1] = v.y;
            Tsm[row][col4*4+2] = v.z; Tsm[row][col4*4+3] = v.w;
        }
        __syncthreads();
        #pragma unroll 16
        for (int k = 0; k < 64; k++)
            acc = fmaf(Aq[w*NT + kc + k], Tsm[c][k], acc);
        __syncthreads();
    }
    int p = q*WAYS + w;
    g_pq[(size_t)p*CIN + c0 + c] = (acc - g_bq[p]) * (1.f/NT);
}

// ---------------- k7: cosine similarity / TEMP ----------------
__global__ void k7_sim(float* __restrict__ out) {
    int t = threadIdx.x, lane = t & 31, wp = t >> 5;
    int p = blockIdx.x*8 + wp;
    if (p >= NP) return;
    float d = 0, ns = 0, nq = 0;
    #pragma unroll
    for (int j = 0; j < 20; j++) {
        int cidx = lane + 32*j;
        float a = g_ps[(size_t)p*CIN + cidx];
        float b = g_pq[(size_t)p*CIN + cidx];
        d = fmaf(a, b, d); ns = fmaf(a, a, ns); nq = fmaf(b, b, nq);
    }
    #pragma unroll
    for (int off = 16; off > 0; off >>= 1) {
        d  += __shfl_xor_sync(0xffffffff, d,  off);
        ns += __shfl_xor_sync(0xffffffff, ns, off);
        nq += __shfl_xor_sync(0xffffffff, nq, off);
    }
    if (lane == 0)
        out[p] = d / (fmaxf(sqrtf(ns), 1e-8f) * fmaxf(sqrtf(nq), 1e-8f)) * 5.0f; // /TEMP(0.2)
}

// ---------------- launch ----------------
extern "C" void kernel_launch(void* const* d_in, const int* in_sizes, int n_in,
                              void* d_out, int out_size) {
    const float* spt   = (const float*)d_in[0];
    const float* qry   = (const float*)d_in[1];
    const float* w     = (const float*)d_in[2];
    const float* gamma = (const float*)d_in[3];
    const float* beta  = (const float*)d_in[4];
    const float* mean  = (const float*)d_in[5];
    const float* var   = (const float*)d_in[6];
    float* out = (float*)d_out;

    k0_prep<<<1, 256>>>(w, gamma, beta, mean, var);
    dim3 g1(4, 80);
    k1_feat<<<g1, 128>>>(spt, qry);
    cudaFuncSetAttribute(k2_corr, cudaFuncAttributeMaxDynamicSharedMemorySize, 65536);
    dim3 g2(4, 4, NP);
    k2_corr<<<g2, 256, 65536>>>();
    k3_stats<<<NP, 256>>>();
    k4_z<<<NP, 256>>>();
    k5_attn<<<NP, 256>>>();
    k5b_bias<<<47, 256>>>();
    dim3 g6a(10, 5);
    k6a_pool_s<<<g6a, 256>>>(spt);
    dim3 g6b(10, 75);
    k6b_pool_q<<<g6b, 320>>>(qry);
    k7_sim<<<47, 256>>>(out);
}

// round 3
// speedup vs baseline: 1.6103x; 1.6103x over previous
#include <cuda_runtime.h>
#include <cuda_fp16.h>
#include <math.h>
#include <stdint.h>

#define WAYS 5
#define NQ 75
#define CIN 640
#define NT 512
#define CP 64
#define NP (NQ*WAYS)   // 375

// ---------------- scratch (__device__ globals; no runtime allocation) ----------------
__device__ float g_wt[CIN*CP];          // transposed conv weight [c][o]
__device__ float g_wsum[CP];
__device__ float g_bnscale[CP];
__device__ float g_bnshift[CP];
__device__ __align__(16) __half g_fs[WAYS*NT*CP];   // [w][i][o] fp16
__device__ __align__(16) __half g_fq[NQ*NT*CP];     // [q][k][o] fp16
__device__ float g_mu_s[WAYS*NT];
__device__ float g_mu_q[NQ*NT];
__device__ __align__(16) __half g_corr_h[(size_t)NP*NT*NT];   // 196 MB fp16
// per-tile stats partials: [p][idx 512][4 blocks]
__device__ float g_prs[(size_t)NP*NT*4], g_prq[(size_t)NP*NT*4];
__device__ float g_pcs[(size_t)NP*NT*4], g_pcq[(size_t)NP*NT*4];
__device__ float g_rs[NP*NT], g_cs[NP*NT];     // softmax scales 1/(5*sigma)
__device__ float g_as[NP*NT], g_aq[NP*NT];
__device__ float g_bs[NP], g_bq[NP];
__device__ float g_ps[NP*CIN], g_pq[NP*CIN];

// ---------------- helpers ----------------
__device__ __forceinline__ uint32_t smem_u32(const void* p) {
    return (uint32_t)__cvta_generic_to_shared(p);
}
__device__ __forceinline__ void ldmatrix_x4(uint32_t* d, uint32_t addr) {
    asm volatile("ldmatrix.sync.aligned.m8n8.x4.shared.b16 {%0,%1,%2,%3}, [%4];"
                 : "=r"(d[0]), "=r"(d[1]), "=r"(d[2]), "=r"(d[3]) : "r"(addr));
}
__device__ __forceinline__ void mma16816(float* c, const uint32_t* a, uint32_t b0, uint32_t b1) {
    asm volatile("mma.sync.aligned.m16n8k16.row.col.f32.f16.f16.f32 "
                 "{%0,%1,%2,%3}, {%4,%5,%6,%7}, {%8,%9}, {%0,%1,%2,%3};"
                 : "+f"(c[0]), "+f"(c[1]), "+f"(c[2]), "+f"(c[3])
                 : "r"(a[0]), "r"(a[1]), "r"(a[2]), "r"(a[3]), "r"(b0), "r"(b1));
}
// swizzled index into the 128x128 fp16 output tile
__device__ __forceinline__ int cs_idx(int r, int c) {
    return r*128 + ((((c >> 3) ^ (r & 15))) << 3) + (c & 7);
}

// ---------------- k0: weight transpose + row sums + BN fold ----------------
__global__ void k0_prep(const float* __restrict__ w, const float* __restrict__ gamma,
                        const float* __restrict__ beta, const float* __restrict__ mean,
                        const float* __restrict__ var) {
    int t = threadIdx.x;
    for (int idx = t; idx < CIN*CP; idx += blockDim.x) {
        int c = idx / CP, o = idx % CP;
        g_wt[idx] = w[o*CIN + c];
    }
    if (t < CP) {
        float s = 0.f;
        const float* row = w + t*CIN;
        #pragma unroll 8
        for (int c = 0; c < CIN; c++) s += row[c];
        g_wsum[t] = s;
        float sc = gamma[t] * rsqrtf(var[t] + 1e-5f);
        g_bnscale[t] = sc;
        g_bnshift[t] = beta[t] - mean[t]*sc;
    }
}

// ---------------- k1: center+conv+BN+ReLU+L2norm features -> fp16 [token][o] ----------------
__global__ void k1_feat(const float* __restrict__ spt, const float* __restrict__ qry) {
    __shared__ float wb[16][CP];
    __shared__ float sc[CP], sh[CP], ws[CP];
    int t = threadIdx.x;               // 128
    int b = blockIdx.y;
    int i = blockIdx.x*128 + t;
    const float* X = (b < WAYS) ? (spt + (size_t)b*CIN*NT)
                                : (qry + (size_t)(b-WAYS)*CIN*NT);
    if (t < CP) { sc[t] = g_bnscale[t]; sh[t] = g_bnshift[t]; ws[t] = g_wsum[t]; }
    float acc[CP];
    #pragma unroll
    for (int o = 0; o < CP; o++) acc[o] = 0.f;
    float xsum = 0.f;
    for (int c0 = 0; c0 < CIN; c0 += 16) {
        __syncthreads();
        #pragma unroll
        for (int j = 0; j < 8; j++) {
            int idx = t + j*128;
            ((float*)wb)[idx] = g_wt[c0*CP + idx];
        }
        __syncthreads();
        #pragma unroll 4
        for (int cc = 0; cc < 16; cc++) {
            float x = X[(size_t)(c0+cc)*NT + i];
            xsum += x;
            #pragma unroll
            for (int o = 0; o < CP; o++) acc[o] = fmaf(x, wb[cc][o], acc[o]);
        }
    }
    float mu = xsum * (1.f/CIN);
    if (b < WAYS) g_mu_s[b*NT + i] = mu; else g_mu_q[(b-WAYS)*NT + i] = mu;
    float nrm = 0.f;
    #pragma unroll
    for (int o = 0; o < CP; o++) {
        float v = (acc[o] - mu*ws[o]) * sc[o] + sh[o];
        v = fmaxf(v, 0.f);
        acc[o] = v;
        nrm = fmaf(v, v, nrm);
    }
    float inv = 1.f / fmaxf(sqrtf(nrm), 1e-8f);
    __half* F = ((b < WAYS) ? (g_fs + (size_t)b*NT*CP) : (g_fq + (size_t)(b-WAYS)*NT*CP))
                + (size_t)i*CP;
    #pragma unroll
    for (int o = 0; o < CP; o += 2)
        *(__half2*)(F + o) = __floats2half2_rn(acc[o]*inv, acc[o+1]*inv);
}

// ---------------- k2: tensor-core corr GEMM + fp16 store + stats partials ----------------
// grid (4 kblk, 4 iblk, 375 p), 256 threads = 8 warps (4x2 warp tile of 32x64)
__global__ void __launch_bounds__(256) k2_corr() {
    __shared__ __align__(16) __half S[16384];   // As[128][64] + Bs[128][64]; reused as Cs[128][128]
    __half* As = S;
    __half* Bs = S + 8192;
    int t = threadIdx.x, ln = t & 31, wid = t >> 5;
    int p = blockIdx.z, q = p / WAYS, w = p % WAYS;
    int i0 = blockIdx.y * 128, k0 = blockIdx.x * 128;
    const __half* Ag = g_fs + (size_t)(w*NT + i0)*CP;
    const __half* Bg = g_fq + (size_t)(q*NT + k0)*CP;
    #pragma unroll
    for (int j = 0; j < 4; j++) {
        int l = t + 256*j;
        int r = l >> 3, ch = l & 7;
        int sw = ch ^ (r & 7);
        *(int4*)(As + r*64 + sw*8) = *(const int4*)(Ag + r*64 + ch*8);
        *(int4*)(Bs + r*64 + sw*8) = *(const int4*)(Bg + r*64 + ch*8);
    }
    __syncthreads();
    int wm = wid >> 1, wn = wid & 1;
    float acc[2][8][4];
    #pragma unroll
    for (int mi = 0; mi < 2; mi++)
        #pragma unroll
        for (int nj = 0; nj < 8; nj++)
            #pragma unroll
            for (int e = 0; e < 4; e++) acc[mi][nj][e] = 0.f;
    #pragma unroll
    for (int ks = 0; ks < 4; ks++) {
        uint32_t a[2][4];
        #pragma unroll
        for (int mi = 0; mi < 2; mi++) {
            int base = wm*32 + mi*16;
            int r = base + (ln & 7) + ((ln >> 3) & 1)*8;
            int ch = ks*2 + (ln >> 4);
            ldmatrix_x4(a[mi], smem_u32(As + r*64 + ((ch ^ (r & 7))*8)));
        }
        uint32_t b[4][4];
        #pragma unroll
        for (int njp = 0; njp < 4; njp++) {
            int nb = wn*64 + njp*16;
            int r = nb + (ln & 7) + ((ln >> 4) ? 8 : 0);
            int ch = ks*2 + ((ln >> 3) & 1);
            ldmatrix_x4(b[njp], smem_u32(Bs + r*64 + ((ch ^ (r & 7))*8)));
        }
        #pragma unroll
        for (int mi = 0; mi < 2; mi++)
            #pragma unroll
            for (int njp = 0; njp < 4; njp++) {
                mma16816(acc[mi][njp*2],   a[mi], b[njp][0], b[njp][1]);
                mma16816(acc[mi][njp*2+1], a[mi], b[njp][2], b[njp][3]);
            }
    }
    __syncthreads();
    __half* Cs = S;   // 128x128 fp16 tile, swizzled
    #pragma unroll
    for (int mi = 0; mi < 2; mi++)
        #pragma unroll
        for (int nj = 0; nj < 8; nj++) {
            int r = wm*32 + mi*16 + (ln >> 2);
            int c = wn*64 + nj*8 + 2*(ln & 3);
            *(__half2*)(Cs + cs_idx(r, c))   = __floats2half2_rn(acc[mi][nj][0], acc[mi][nj][1]);
            *(__half2*)(Cs + cs_idx(r+8, c)) = __floats2half2_rn(acc[mi][nj][2], acc[mi][nj][3]);
        }
    __syncthreads();
    // stats partials from the fp16-rounded tile (consistent with later reads)
    if (t < 128) {             // column c = t: reduce over i (rows)
        float s = 0.f, s2 = 0.f;
        for (int r = 0; r < 128; r++) {
            float v = __half2float(Cs[cs_idx(r, t)]);
            s += v; s2 = fmaf(v, v, s2);
        }
        size_t idx = ((size_t)p*NT + (k0 + t))*4 + blockIdx.y;
        g_pcs[idx] = s; g_pcq[idx] = s2;
    } else {                   // row r = t-128: reduce over k (cols)
        int r = t - 128;
        float s = 0.f, s2 = 0.f;
        for (int c = 0; c < 128; c += 2) {
            float2 v = __half22float2(*(__half2*)(Cs + cs_idx(r, c)));
            s += v.x + v.y;
            s2 = fmaf(v.x, v.x, fmaf(v.y, v.y, s2));
        }
        size_t idx = ((size_t)p*NT + (i0 + r))*4 + blockIdx.x;
        g_prs[idx] = s; g_prq[idx] = s2;
    }
    // coalesced fp16 write of the tile
    __half* out = g_corr_h + (size_t)p*NT*NT;
    #pragma unroll
    for (int j = 0; j < 8; j++) {
        int l = t + 256*j;
        int r = l >> 4, ch = l & 15;
        *(int4*)(out + (size_t)(i0 + r)*NT + k0 + ch*8) =
            *(int4*)(Cs + r*128 + ((ch ^ (r & 15))*8));
    }
}

// ---------------- k3r: reduce stats partials -> softmax scales (no max needed) ----------------
__global__ void k3r_reduce() {
    int p = blockIdx.x, t = threadIdx.x;
    #pragma unroll
    for (int u = 0; u < 2; u++) {
        int x = t + 256*u;
        size_t ri = (size_t)p*NT + x;
        float s  = g_prs[ri*4] + g_prs[ri*4+1] + g_prs[ri*4+2] + g_prs[ri*4+3];
        float s2 = g_prq[ri*4] + g_prq[ri*4+1] + g_prq[ri*4+2] + g_prq[ri*4+3];
        float m = s * (1.f/NT);
        float var = (s2 - NT*m*m) * (1.f/(NT-1));
        g_rs[ri] = 1.f / (5.0f * sqrtf(var + 1e-5f));
        s  = g_pcs[ri*4] + g_pcs[ri*4+1] + g_pcs[ri*4+2] + g_pcs[ri*4+3];
        s2 = g_pcq[ri*4] + g_pcq[ri*4+1] + g_pcq[ri*4+2] + g_pcq[ri*4+3];
        m = s * (1.f/NT);
        var = (s2 - NT*m*m) * (1.f/(NT-1));
        g_cs[ri] = 1.f / (5.0f * sqrtf(var + 1e-5f));
    }
}

// ---------------- k45: fused Z (partition sums) + attention sums, fp16 corr, 2 sweeps ----------
__global__ void __launch_bounds__(256) k45_fused() {
    __shared__ __align__(16) __half tile[8*NT];
    __shared__ float sRS[NT], sCS[NT], sZr[NT], sZcInv[NT];
    int t = threadIdx.x, ln = t & 31, wp = t >> 5;
    int p = blockIdx.x;
    const __half* M = g_corr_h + (size_t)p*NT*NT;
    #pragma unroll
    for (int u = 0; u < 2; u++) {
        int x = t + 256*u;
        sRS[x] = g_rs[(size_t)p*NT + x];
        sCS[x] = g_cs[(size_t)p*NT + x];
    }
    __syncthreads();
    float cs0 = sCS[t], cs1 = sCS[t + 256];
    float zc0 = 0.f, zc1 = 0.f;
    for (int blk = 0; blk < 64; blk++) {
        const int4* src = (const int4*)(M + (size_t)blk*8*NT);
        ((int4*)tile)[t] = src[t];
        ((int4*)tile)[t + 256] = src[t + 256];
        __syncthreads();
        #pragma unroll
        for (int r = 0; r < 8; r++) {
            float v0 = __half2float(tile[r*NT + t]);
            float v1 = __half2float(tile[r*NT + t + 256]);
            zc0 += __expf(v0 * cs0);
            zc1 += __expf(v1 * cs1);
        }
        int i = blk*8 + wp;
        float rsv = sRS[i];
        float zr = 0.f;
        #pragma unroll
        for (int j = 0; j < 16; j++) {
            float v = __half2float(tile[wp*NT + ln + 32*j]);
            zr += __expf(v * rsv);
        }
        #pragma unroll
        for (int off = 16; off > 0; off >>= 1) zr += __shfl_xor_sync(0xffffffff, zr, off);
        if (ln == 0) sZr[i] = zr;
        __syncthreads();
    }
    sZcInv[t] = 1.f / zc0;
    sZcInv[t + 256] = 1.f / zc1;
    __syncthreads();
    #pragma unroll
    for (int u = 0; u < 2; u++) { int x = t + 256*u; sZr[x] = 1.f / sZr[x]; }
    __syncthreads();
    float aq0 = 0.f, aq1 = 0.f;
    for (int blk = 0; blk < 64; blk++) {
        const int4* src = (const int4*)(M + (size_t)blk*8*NT);
        ((int4*)tile)[t] = src[t];
        ((int4*)tile)[t + 256] = src[t + 256];
        __syncthreads();
        #pragma unroll
        for (int r = 0; r < 8; r++) {
            int i = blk*8 + r;
            float rsv = sRS[i], zri = sZr[i];
            float v0 = __half2float(tile[r*NT + t]);
            float v1 = __half2float(tile[r*NT + t + 256]);
            aq0 += __expf(v0 * rsv) * zri;
            aq1 += __expf(v1 * rsv) * zri;
        }
        float as = 0.f;
        #pragma unroll
        for (int j = 0; j < 16; j++) {
            int k = ln + 32*j;
            float v = __half2float(tile[wp*NT + k]);
            as += __expf(v * sCS[k]) * sZcInv[k];
        }
        #pragma unroll
        for (int off = 16; off > 0; off >>= 1) as += __shfl_xor_sync(0xffffffff, as, off);
        if (ln == 0) g_as[(size_t)p*NT + blk*8 + wp] = as;
        __syncthreads();
    }
    g_aq[(size_t)p*NT + t] = aq0;
    g_aq[(size_t)p*NT + t + 256] = aq1;
}

// ---------------- k5b: mean-correction terms ----------------
__global__ void k5b_bias() {
    int t = threadIdx.x, lane = t & 31, wp = t >> 5;
    int p = blockIdx.x*8 + wp;
    if (p >= NP) return;
    int q = p / WAYS, w = p % WAYS;
    float bs = 0, bq = 0;
    #pragma unroll
    for (int j = 0; j < 16; j++) {
        int k = lane + 32*j;
        bs = fmaf(g_as[p*NT + k], g_mu_s[w*NT + k], bs);
        bq = fmaf(g_aq[p*NT + k], g_mu_q[q*NT + k], bq);
    }
    #pragma unroll
    for (int off = 16; off > 0; off >>= 1) {
        bs += __shfl_xor_sync(0xffffffff, bs, off);
        bq += __shfl_xor_sync(0xffffffff, bq, off);
    }
    if (lane == 0) { g_bs[p] = bs; g_bq[p] = bq; }
}

// ---------------- k6a: support pooling ----------------
__global__ void k6a_pool_s(const float* __restrict__ spt) {
    __shared__ float Tsm[64][65];
    __shared__ float Asm[75][64];
    int t = threadIdx.x;
    int w = blockIdx.y, c0 = blockIdx.x*64;
    int c = t & 63, qg = t >> 6;
    float acc[19];
    #pragma unroll
    for (int j = 0; j < 19; j++) acc[j] = 0.f;
    const float* T = spt + (size_t)w*CIN*NT;
    for (int ic = 0; ic < NT; ic += 64) {
        #pragma unroll
        for (int j = 0; j < 4; j++) {
            int f4 = t + 256*j;
            int row = f4 >> 4, col4 = f4 & 15;
            float4 v = *(const float4*)(T + (size_t)(c0+row)*NT + ic + col4*4);
            Tsm[row][col4*4+0] = v.x; Tsm[row][col4*4+1] = v.y;
            Tsm[row][col4*4+2] = v.z; Tsm[row][col4*4+3] = v.w;
        }
        for (int idx = t; idx < 75*64; idx += 256) {
            int qq = idx >> 6, ii = idx & 63;
            Asm[qq][ii] = g_as[(size_t)(qq*WAYS + w)*NT + ic + ii];
        }
        __syncthreads();
        #pragma unroll 8
        for (int i = 0; i < 64; i++) {
            float tv = Tsm[c][i];
            #pragma unroll
            for (int j = 0; j < 19; j++) {
                int qq = qg + 4*j;
                if (qq < 75) acc[j] = fmaf(Asm[qq][i], tv, acc[j]);
            }
        }
        __syncthreads();
    }
    #pragma unroll
    for (int j = 0; j < 19; j++) {
        int qq = qg + 4*j;
        if (qq < 75) {
            int p = qq*WAYS + w;
            g_ps[(size_t)p*CIN + c0 + c] = (acc[j] - g_bs[p]) * (1.f/NT);
        }
    }
}

// ---------------- k6b: query pooling ----------------
__global__ void k6b_pool_q(const float* __restrict__ qry) {
    __shared__ float Tsm[64][65];
    __shared__ float Aq[5*NT];
    int t = threadIdx.x;
    int q = blockIdx.y, c0 = blockIdx.x*64;
    int c = t & 63, w = t >> 6;
    for (int idx = t; idx < 5*NT; idx += 320) {
        int ww = idx >> 9, kk = idx & 511;
        Aq[idx] = g_aq[(size_t)(q*WAYS + ww)*NT + kk];
    }
    const float* T = qry + (size_t)q*CIN*NT;
    float acc = 0.f;
    for (int kc = 0; kc < NT; kc += 64) {
        for (int f4 = t; f4 < 1024; f4 += 320) {
            int row = f4 >> 4, col4 = f4 & 15;
            float4 v = *(const float4*)(T + (size_t)(c0+row)*NT + kc + col4*4);
            Tsm[row][col4*4+0] = v.x; Tsm[row][col4*4+1] = v.y;
            Tsm[row][col4*4+2] = v.z; Tsm[row][col4*4+3] = v.w;
        }
        __syncthreads();
        #pragma unroll 16
        for (int k = 0; k < 64; k++)
            acc = fmaf(Aq[w*NT + kc + k], Tsm[c][k], acc);
        __syncthreads();
    }
    int p = q*WAYS + w;
    g_pq[(size_t)p*CIN + c0 + c] = (acc - g_bq[p]) * (1.f/NT);
}

// ---------------- k7: cosine similarity / TEMP ----------------
__global__ void k7_sim(float* __restrict__ out) {
    int t = threadIdx.x, lane = t & 31, wp = t >> 5;
    int p = blockIdx.x*8 + wp;
    if (p >= NP) return;
    float d = 0, ns = 0, nq = 0;
    #pragma unroll
    for (int j = 0; j < 20; j++) {
        int cidx = lane + 32*j;
        float a = g_ps[(size_t)p*CIN + cidx];
        float b = g_pq[(size_t)p*CIN + cidx];
        d = fmaf(a, b, d); ns = fmaf(a, a, ns); nq = fmaf(b, b, nq);
    }
    #pragma unroll
    for (int off = 16; off > 0; off >>= 1) {
        d  += __shfl_xor_sync(0xffffffff, d,  off);
        ns += __shfl_xor_sync(0xffffffff, ns, off);
        nq += __shfl_xor_sync(0xffffffff, nq, off);
    }
    if (lane == 0)
        out[p] = d / (fmaxf(sqrtf(ns), 1e-8f) * fmaxf(sqrtf(nq), 1e-8f)) * 5.0f;
}

// ---------------- launch ----------------
extern "C" void kernel_launch(void* const* d_in, const int* in_sizes, int n_in,
                              void* d_out, int out_size) {
    const float* spt   = (const float*)d_in[0];
    const float* qry   = (const float*)d_in[1];
    const float* w     = (const float*)d_in[2];
    const float* gamma = (const float*)d_in[3];
    const float* beta  = (const float*)d_in[4];
    const float* mean  = (const float*)d_in[5];
    const float* var   = (const float*)d_in[6];
    float* out = (float*)d_out;

    k0_prep<<<1, 256>>>(w, gamma, beta, mean, var);
    dim3 g1(4, 80);
    k1_feat<<<g1, 128>>>(spt, qry);
    dim3 g2(4, 4, NP);
    k2_corr<<<g2, 256>>>();
    k3r_reduce<<<NP, 256>>>();
    k45_fused<<<NP, 256>>>();
    k5b_bias<<<47, 256>>>();
    dim3 g6a(10, 5);
    k6a_pool_s<<<g6a, 256>>>(spt);
    dim3 g6b(10, 75);
    k6b_pool_q<<<g6b, 320>>>(qry);
    k7_sim<<<47, 256>>>(out);
}